// round 6
// baseline (speedup 1.0000x reference)
#include <cuda_runtime.h>

// EntmaxBisect: alpha=1.5, 50-iter bisection over last dim (4096), rows = 8*2048 = 16384.
//
// Math reduction: with p = 1/4095, every positive term (Xs_i - t)^p lies in
// (0.975, 1], so sum(Z) >= 1  <=>  count(Xs > t) >= 2  <=>  second_largest(Xs) > t.
// Bisection depends only on the row's top-2; replicated bit-exactly on the
// reference's fp32 lattice (returns the final TESTED t). Top-2 computed on raw
// X, halved afterwards (0.5x exact & monotone); u = fmaf(0.5,x,-t) == (0.5x)-t.
//
// Structure: persistent CTAs (608 = 4/SM x 152 SM) with next-row prefetch
// issued before the barrier-phased compute. KEY sparsity hoist: a thread whose
// private max gives u <= 0 has ALL 8 elements inactive (>99.5% of threads) —
// it skips the entire Z/pow/normalize path and just stores zeros.

#define D        4096
#define THREADS  512
#define NWARPS   16
#define N_ITER   50
#define GRID     608

__global__ __launch_bounds__(THREADS, 4)
void entmax_bisect_kernel(const float* __restrict__ X, float* __restrict__ out,
                          int nrows)
{
    const int tid  = threadIdx.x;
    const int lane = tid & 31;
    const int wid  = tid >> 5;

    __shared__ float sm1[NWARPS];
    __shared__ float sm2[NWARPS];
    __shared__ alignas(16) float ssum[NWARPS];
    __shared__ float sbc;

    const float4* __restrict__ x4 = reinterpret_cast<const float4*>(X);
    float4* __restrict__ o4 = reinterpret_cast<float4*>(out);

    int row = blockIdx.x;
    if (row >= nrows) return;

    size_t base = (size_t)row * (D / 4);
    float4 v0 = x4[base + tid];
    float4 v1 = x4[base + tid + THREADS];

    const float NEG_INF = -__int_as_float(0x7f800000);

    while (true) {
        const int  nrow = row + GRID;
        const bool more = (nrow < nrows);
        // ---- prefetch next row NOW; overlaps all phases below ----
        const size_t pb = (size_t)(more ? nrow : row) * (D / 4);
        float4 nv0 = x4[pb + tid];
        float4 nv1 = x4[pb + tid + THREADS];

        // ---- per-thread top-2 of raw X (branchless) ----
        float tm1 = NEG_INF, tm2 = NEG_INF;
        {
            float v, lo;
            v = v0.x; lo = fminf(tm1, v); tm1 = fmaxf(tm1, v); tm2 = fmaxf(tm2, lo);
            v = v0.y; lo = fminf(tm1, v); tm1 = fmaxf(tm1, v); tm2 = fmaxf(tm2, lo);
            v = v0.z; lo = fminf(tm1, v); tm1 = fmaxf(tm1, v); tm2 = fmaxf(tm2, lo);
            v = v0.w; lo = fminf(tm1, v); tm1 = fmaxf(tm1, v); tm2 = fmaxf(tm2, lo);
            v = v1.x; lo = fminf(tm1, v); tm1 = fmaxf(tm1, v); tm2 = fmaxf(tm2, lo);
            v = v1.y; lo = fminf(tm1, v); tm1 = fmaxf(tm1, v); tm2 = fmaxf(tm2, lo);
            v = v1.z; lo = fminf(tm1, v); tm1 = fmaxf(tm1, v); tm2 = fmaxf(tm2, lo);
            v = v1.w; lo = fminf(tm1, v); tm1 = fmaxf(tm1, v); tm2 = fmaxf(tm2, lo);
        }

        // ---- warp top-2 reduce (keep tm1 = this thread's own max!) ----
        float w1 = tm1, w2 = tm2;
        #pragma unroll
        for (int off = 16; off > 0; off >>= 1) {
            float b1 = __shfl_down_sync(0xffffffffu, w1, off);
            float b2 = __shfl_down_sync(0xffffffffu, w2, off);
            float lo = fminf(w1, b1);
            w1 = fmaxf(w1, b1);
            w2 = fmaxf(fmaxf(w2, b2), lo);
        }
        if (lane == 0) { sm1[wid] = w1; sm2[wid] = w2; }
        __syncthreads();                                        // sync1

        // ---- warp 0: butterfly combine of the 16 warp partials + bisection ----
        if (wid == 0) {
            float M = (lane < NWARPS) ? sm1[lane] : NEG_INF;
            float S = (lane < NWARPS) ? sm2[lane] : NEG_INF;
            #pragma unroll
            for (int off = 8; off > 0; off >>= 1) {
                float b1 = __shfl_xor_sync(0xffffffffu, M, off);
                float b2 = __shfl_xor_sync(0xffffffffu, S, off);
                float lo = fminf(M, b1);
                M = fmaxf(M, b1);
                S = fmaxf(fmaxf(S, b2), lo);
            }
            M *= 0.5f;                        // exact: top-2 of Xs = 0.5*top-2 of X
            S *= 0.5f;
            // scalar fp32 bisection, bit-faithful to the reference lattice
            // (all 32 lanes run it redundantly; SIMT-free)
            float tmin = M - 1.0f;
            float tmax = M - 0.015625f;       // M - 4096^(1-1.5), exact constant
            float diff = tmax - tmin;
            float t = tmin;
            #pragma unroll 1
            for (int i = 0; i < N_ITER; i++) {
                diff = diff * 0.5f;
                t = tmin + diff;
                if (S > t) tmin = t;          // == (sum(Z)-1 >= 0)
            }
            if (lane == 0) sbc = t;           // final TESTED t, as in reference
        }
        __syncthreads();                                        // sync2

        const float t = sbc;
        const float p = 1.0f / 4095.0f;       // == fp32(1/(d-1))

        // ---- sparsity hoist: thread active iff its own max element is above t
        const bool active = (fmaf(0.5f, tm1, -t) > 0.0f);

        float lsum = 0.0f;
        float4 z0, z1;
        if (active) {                          // ~1-2 threads per ROW of 512
            float u, z;
            u = fmaf(0.5f, v0.x, -t); z = (u > 0.0f) ? __powf(u, p) : 0.0f; z0.x = z; lsum += z;
            u = fmaf(0.5f, v0.y, -t); z = (u > 0.0f) ? __powf(u, p) : 0.0f; z0.y = z; lsum += z;
            u = fmaf(0.5f, v0.z, -t); z = (u > 0.0f) ? __powf(u, p) : 0.0f; z0.z = z; lsum += z;
            u = fmaf(0.5f, v0.w, -t); z = (u > 0.0f) ? __powf(u, p) : 0.0f; z0.w = z; lsum += z;
            u = fmaf(0.5f, v1.x, -t); z = (u > 0.0f) ? __powf(u, p) : 0.0f; z1.x = z; lsum += z;
            u = fmaf(0.5f, v1.y, -t); z = (u > 0.0f) ? __powf(u, p) : 0.0f; z1.y = z; lsum += z;
            u = fmaf(0.5f, v1.z, -t); z = (u > 0.0f) ? __powf(u, p) : 0.0f; z1.z = z; lsum += z;
            u = fmaf(0.5f, v1.w, -t); z = (u > 0.0f) ? __powf(u, p) : 0.0f; z1.w = z; lsum += z;
        }
        #pragma unroll
        for (int off = 16; off > 0; off >>= 1)
            lsum += __shfl_down_sync(0xffffffffu, lsum, off);
        if (lane == 0) ssum[wid] = lsum;
        __syncthreads();                                        // sync3

        const size_t ob = (size_t)row * (D / 4);
        if (active) {
            // combine 16 warp partials via 4x LDS.128
            const float4* s4 = reinterpret_cast<const float4*>(ssum);
            float4 a = s4[0], b = s4[1], c = s4[2], d = s4[3];
            float tot = ((a.x + a.y) + (a.z + a.w)) + ((b.x + b.y) + (b.z + b.w))
                      + ((c.x + c.y) + (c.z + c.w)) + ((d.x + d.y) + (d.z + d.w));
            const float inv = 1.0f / tot;
            float4 r0, r1;
            r0.x = z0.x * inv; r0.y = z0.y * inv; r0.z = z0.z * inv; r0.w = z0.w * inv;
            r1.x = z1.x * inv; r1.y = z1.y * inv; r1.z = z1.z * inv; r1.w = z1.w * inv;
            __stcs(&o4[ob + tid], r0);
            __stcs(&o4[ob + tid + THREADS], r1);
        } else {
            const float4 zr = make_float4(0.0f, 0.0f, 0.0f, 0.0f);
            __stcs(&o4[ob + tid], zr);
            __stcs(&o4[ob + tid + THREADS], zr);
        }

        if (!more) break;
        v0 = nv0; v1 = nv1;
        row = nrow;
    }
}

extern "C" void kernel_launch(void* const* d_in, const int* in_sizes, int n_in,
                              void* d_out, int out_size)
{
    const float* X = (const float*)d_in[0];
    float* out = (float*)d_out;
    const int n = in_sizes[0];          // 8*2048*4096
    const int rows = n / D;             // 16384
    entmax_bisect_kernel<<<GRID, THREADS>>>(X, out, rows);
}